// round 2
// baseline (speedup 1.0000x reference)
#include <cuda_runtime.h>
#include <cuda_bf16.h>
#include <math.h>

// Problem constants
constexpr int B   = 2;
constexpr int S   = 2048;
constexpr int HID = 2048;
constexpr int H   = 16;
constexpr int KV  = 4;
constexpr int D   = 128;
constexpr int G   = H / KV;           // 4
constexpr float EPS = 1e-6f;
constexpr float SCALE = 0.08838834764831845f; // 128^-0.5

// ---------------- scratch (static device globals; no runtime alloc) -------
__device__ float g_qg  [(size_t)B * S * 2 * H * D];   // [B,S,4096] q||gate
__device__ float g_kbuf[(size_t)B * S * KV * D];      // [B,S,512]
__device__ float g_vbuf[(size_t)B * S * KV * D];      // [B,S,512]
__device__ float g_qr  [(size_t)B * H * S * D];       // [B,H,S,D] q rope'd
__device__ float g_kr  [(size_t)B * KV * S * D];      // [B,KV,S,D]
__device__ float g_vt  [(size_t)B * KV * S * D];      // [B,KV,S,D]
__device__ float g_attn[(size_t)B * S * H * D];       // [B,S,H*D] gated attn

// ---------------- SGEMM: C[M,N] = A[M,K] @ B[K,N], all row-major ----------
// 128x128 tile, 8-wide K step, double-buffered smem (1 sync / K-step).
// Requires M%128==0, N%128==0, K%16==0 (true for all call sites).
__global__ __launch_bounds__(256) void sgemm_kernel(
    const float* __restrict__ A, const float* __restrict__ Bm,
    float* __restrict__ C, int M, int N, int K)
{
    __shared__ float As[2][8][132];
    __shared__ float Bs[2][8][132];

    const int tid = threadIdx.x;
    const int m0 = blockIdx.y * 128;
    const int n0 = blockIdx.x * 128;
    const int tm = tid >> 4;        // 0..15
    const int tn = tid & 15;        // 0..15

    const int arow = tid >> 1;          // 0..127
    const int akq  = (tid & 1) * 4;     // 0 or 4
    const int brow = tid >> 5;          // 0..7
    const int bcol = (tid & 31) * 4;    // 0..124

    const float* Aptr = A + (size_t)(m0 + arow) * K + akq;
    const float* Bptr = Bm + (size_t)brow * N + n0 + bcol;

    float acc[8][8];
#pragma unroll
    for (int i = 0; i < 8; i++)
#pragma unroll
        for (int j = 0; j < 8; j++) acc[i][j] = 0.f;

    // preload tile 0
    float4 av = *(const float4*)(Aptr);
    float4 bv = *(const float4*)(Bptr);
    As[0][akq + 0][arow] = av.x;
    As[0][akq + 1][arow] = av.y;
    As[0][akq + 2][arow] = av.z;
    As[0][akq + 3][arow] = av.w;
    *(float4*)&Bs[0][brow][bcol] = bv;
    __syncthreads();

    int buf = 0;
    for (int k0 = 0; k0 < K; k0 += 8) {
        // prefetch next K-tile into registers (overlaps with compute below)
        const bool more = (k0 + 8) < K;
        if (more) {
            av = *(const float4*)(Aptr + k0 + 8);
            bv = *(const float4*)(Bptr + (size_t)(k0 + 8) * N);
        }

#pragma unroll
        for (int k = 0; k < 8; k++) {
            float ra[8], rb[8];
            *(float4*)(ra)     = *(const float4*)&As[buf][k][tm * 8];
            *(float4*)(ra + 4) = *(const float4*)&As[buf][k][tm * 8 + 4];
            *(float4*)(rb)     = *(const float4*)&Bs[buf][k][tn * 8];
            *(float4*)(rb + 4) = *(const float4*)&Bs[buf][k][tn * 8 + 4];
#pragma unroll
            for (int i = 0; i < 8; i++)
#pragma unroll
                for (int j = 0; j < 8; j++)
                    acc[i][j] += ra[i] * rb[j];
        }

        if (more) {
            // store prefetched tile into the other buffer (disjoint from
            // the buffer peers may still be reading) then one sync.
            As[buf ^ 1][akq + 0][arow] = av.x;
            As[buf ^ 1][akq + 1][arow] = av.y;
            As[buf ^ 1][akq + 2][arow] = av.z;
            As[buf ^ 1][akq + 3][arow] = av.w;
            *(float4*)&Bs[buf ^ 1][brow][bcol] = bv;
            __syncthreads();
            buf ^= 1;
        }
    }

#pragma unroll
    for (int i = 0; i < 8; i++) {
        float* crow = C + (size_t)(m0 + tm * 8 + i) * N + n0 + tn * 8;
        *(float4*)(crow)     = make_float4(acc[i][0], acc[i][1], acc[i][2], acc[i][3]);
        *(float4*)(crow + 4) = make_float4(acc[i][4], acc[i][5], acc[i][6], acc[i][7]);
    }
}

// ---------------- RMSNorm + RoPE + transpose (q, k) and transpose (v) -----
// grid.x = B*S*(H + 2*KV), block = 128 threads (one per d)
__global__ __launch_bounds__(128) void normrope_kernel(
    const float* __restrict__ qg, const float* __restrict__ kbuf,
    const float* __restrict__ vbuf,
    const float* __restrict__ cosb, const float* __restrict__ sinb,
    const float* __restrict__ qw, const float* __restrict__ kw,
    float* __restrict__ q_out, float* __restrict__ k_out,
    float* __restrict__ v_out)
{
    const int unit = blockIdx.x;
    const int d = threadIdx.x;
    const int per_tok = H + 2 * KV;  // 24
    const int tok = unit / per_tok;
    const int sub = unit % per_tok;
    const int b = tok / S, s = tok % S;

    __shared__ float sh[D];
    __shared__ float red[4];

    if (sub >= H + KV) {
        // v transpose only
        int kv = sub - H - KV;
        v_out[(((size_t)(b * KV + kv)) * S + s) * D + d] =
            vbuf[(size_t)tok * (KV * D) + kv * D + d];
        return;
    }

    float x, w;
    size_t out_idx;
    if (sub < H) {
        int h = sub;
        x = qg[(size_t)tok * (2 * H * D) + h * D + d];
        w = qw[d];
        out_idx = (((size_t)(b * H + h)) * S + s) * D + d;
    } else {
        int kv = sub - H;
        x = kbuf[(size_t)tok * (KV * D) + kv * D + d];
        w = kw[d];
        out_idx = (((size_t)(b * KV + kv)) * S + s) * D + d;
    }

    // RMS norm over D=128
    float ss = x * x;
#pragma unroll
    for (int o = 16; o; o >>= 1) ss += __shfl_xor_sync(0xFFFFFFFFu, ss, o);
    if ((d & 31) == 0) red[d >> 5] = ss;
    __syncthreads();
    float tot = red[0] + red[1] + red[2] + red[3];
    float r = rsqrtf(tot * (1.f / D) + EPS);
    float xn = x * r * (1.f + w);

    sh[d] = xn;
    __syncthreads();
    float part = (d < 64) ? -sh[d + 64] : sh[d - 64];
    float c  = cosb[(size_t)tok * D + d];
    float sn = sinb[(size_t)tok * D + d];

    float* dst = (sub < H) ? q_out : k_out;
    dst[out_idx] = xn * c + part * sn;
}

// ---------------- Flash attention (fp32) + sigmoid gate epilogue ----------
// grid = (S/64, B*H), block = 256. Dynamic smem: Qs/Ks/Vs 64x132 + Ss 64x68.
constexpr int ATTN_SMEM = (3 * 64 * 132 + 64 * 68) * 4;  // 118784 B

__global__ __launch_bounds__(256) void attn_kernel(
    const float* __restrict__ qr, const float* __restrict__ kr,
    const float* __restrict__ vr, const float* __restrict__ qg,
    float* __restrict__ attn_out)
{
    extern __shared__ float smem[];
    float* Qs = smem;                // [64][132]
    float* Ks = Qs + 64 * 132;
    float* Vs = Ks + 64 * 132;
    float* Ss = Vs + 64 * 132;       // [64][68]

    const int qb = blockIdx.x, bh = blockIdx.y;
    const int b = bh / H, h = bh % H;
    const int kvh = h / G;
    const int tid = threadIdx.x;
    const int q0 = qb * 64;

    // load Q tile once
    const float* qbase = qr + (((size_t)(b * H + h)) * S + q0) * D;
    for (int i = tid; i < 2048; i += 256) {
        int row = i >> 5, c4 = (i & 31) * 4;
        *(float4*)&Qs[row * 132 + c4] = *(const float4*)(qbase + row * D + c4);
    }

    const int ty = tid >> 4, tx = tid & 15;     // phase-1 16x16 map
    const int qi4 = ty * 4, kj4 = tx * 4;
    const int qrow = tid >> 2, g = tid & 3;     // phase-2 map
    const int gq = q0 + qrow;

    float m = -1e30f, l = 0.f;
    float acc[32];
#pragma unroll
    for (int i = 0; i < 32; i++) acc[i] = 0.f;

    const float* kbase = kr + ((size_t)(b * KV + kvh)) * S * D;
    const float* vbase = vr + ((size_t)(b * KV + kvh)) * S * D;

    for (int kb = 0; kb <= qb; kb++) {
        const int k0 = kb * 64;
        __syncthreads();  // previous iter's Ss/Vs reads done
        for (int i = tid; i < 2048; i += 256) {
            int row = i >> 5, c4 = (i & 31) * 4;
            *(float4*)&Ks[row * 132 + c4] = *(const float4*)(kbase + (size_t)(k0 + row) * D + c4);
            *(float4*)&Vs[row * 132 + c4] = *(const float4*)(vbase + (size_t)(k0 + row) * D + c4);
        }
        __syncthreads();

        // phase 1: 64x64 scores, 4x4 per thread
        float cacc[4][4];
#pragma unroll
        for (int i = 0; i < 4; i++)
#pragma unroll
            for (int j = 0; j < 4; j++) cacc[i][j] = 0.f;

#pragma unroll 8
        for (int dd = 0; dd < D; dd += 4) {
            float4 a[4], bb[4];
#pragma unroll
            for (int i = 0; i < 4; i++) a[i]  = *(const float4*)&Qs[(qi4 + i) * 132 + dd];
#pragma unroll
            for (int j = 0; j < 4; j++) bb[j] = *(const float4*)&Ks[(kj4 + j) * 132 + dd];
#pragma unroll
            for (int i = 0; i < 4; i++)
#pragma unroll
                for (int j = 0; j < 4; j++) {
                    cacc[i][j] += a[i].x * bb[j].x;
                    cacc[i][j] += a[i].y * bb[j].y;
                    cacc[i][j] += a[i].z * bb[j].z;
                    cacc[i][j] += a[i].w * bb[j].w;
                }
        }
#pragma unroll
        for (int i = 0; i < 4; i++)
#pragma unroll
            for (int j = 0; j < 4; j++)
                Ss[(qi4 + i) * 68 + kj4 + j] = cacc[i][j];
        __syncthreads();

        // phase 2a: per-row online softmax; 4 threads per row, 16 keys each
        float pv[16];
        float mb = -1e30f;
#pragma unroll
        for (int jj = 0; jj < 16; jj++) {
            int j = g * 16 + jj;
            float sv = Ss[qrow * 68 + j] * SCALE + ((k0 + j) <= gq ? 0.f : -1e9f);
            pv[jj] = sv;
            mb = fmaxf(mb, sv);
        }
        mb = fmaxf(mb, __shfl_xor_sync(0xFFFFFFFFu, mb, 1));
        mb = fmaxf(mb, __shfl_xor_sync(0xFFFFFFFFu, mb, 2));
        float mnew = fmaxf(m, mb);
        float sum = 0.f;
#pragma unroll
        for (int jj = 0; jj < 16; jj++) {
            pv[jj] = __expf(pv[jj] - mnew);
            sum += pv[jj];
        }
        sum += __shfl_xor_sync(0xFFFFFFFFu, sum, 1);
        sum += __shfl_xor_sync(0xFFFFFFFFu, sum, 2);
        float alpha = __expf(m - mnew);
        l = l * alpha + sum;
        m = mnew;
#pragma unroll
        for (int jj = 0; jj < 16; jj++)
            Ss[qrow * 68 + g * 16 + jj] = pv[jj];
        __syncthreads();

        // phase 2b: O += P @ V (thread owns 32 dims of its row)
#pragma unroll
        for (int i = 0; i < 32; i++) acc[i] *= alpha;
#pragma unroll 8
        for (int j = 0; j < 64; j++) {
            float pj = Ss[qrow * 68 + j];
            const float* vrow = &Vs[j * 132 + g * 32];
#pragma unroll
            for (int i = 0; i < 32; i++) acc[i] += pj * vrow[i];
        }
    }

    // epilogue: normalize + sigmoid gate, write [B,S,H*D]
    const int srow = q0 + qrow;
    const float inv = 1.f / l;
    const size_t gbase = ((size_t)(b * S + srow)) * (2 * H * D) + H * D + h * D + g * 32;
    const size_t obase = ((size_t)(b * S + srow)) * (H * D) + h * D + g * 32;
#pragma unroll
    for (int i = 0; i < 32; i++) {
        float gate = qg[gbase + i];
        float sg = 1.f / (1.f + __expf(-gate));
        attn_out[obase + i] = acc[i] * inv * sg;
    }
}

// ---------------- host launch ---------------------------------------------
extern "C" void kernel_launch(void* const* d_in, const int* in_sizes, int n_in,
                              void* d_out, int out_size)
{
    const float* hidden = (const float*)d_in[0];
    const float* cosb   = (const float*)d_in[1];
    const float* sinb   = (const float*)d_in[2];
    // d_in[3] attention_mask: analytically causal, unused
    const float* Wq = (const float*)d_in[4];
    const float* Wk = (const float*)d_in[5];
    const float* Wv = (const float*)d_in[6];
    const float* Wo = (const float*)d_in[7];
    const float* qw = (const float*)d_in[8];
    const float* kw = (const float*)d_in[9];
    float* out = (float*)d_out;

    void *p_qg, *p_kbuf, *p_vbuf, *p_qr, *p_kr, *p_vt, *p_attn;
    cudaGetSymbolAddress(&p_qg, g_qg);
    cudaGetSymbolAddress(&p_kbuf, g_kbuf);
    cudaGetSymbolAddress(&p_vbuf, g_vbuf);
    cudaGetSymbolAddress(&p_qr, g_qr);
    cudaGetSymbolAddress(&p_kr, g_kr);
    cudaGetSymbolAddress(&p_vt, g_vt);
    cudaGetSymbolAddress(&p_attn, g_attn);

    const int M = B * S;  // 4096 token rows

    // 1) projections
    sgemm_kernel<<<dim3(2 * H * D / 128, M / 128), 256>>>(hidden, Wq, (float*)p_qg, M, 2 * H * D, HID);
    sgemm_kernel<<<dim3(KV * D / 128, M / 128), 256>>>(hidden, Wk, (float*)p_kbuf, M, KV * D, HID);
    sgemm_kernel<<<dim3(KV * D / 128, M / 128), 256>>>(hidden, Wv, (float*)p_vbuf, M, KV * D, HID);

    // 2) rmsnorm + rope + transpose
    normrope_kernel<<<B * S * (H + 2 * KV), 128>>>(
        (const float*)p_qg, (const float*)p_kbuf, (const float*)p_vbuf,
        cosb, sinb, qw, kw,
        (float*)p_qr, (float*)p_kr, (float*)p_vt);

    // 3) flash attention + gate
    cudaFuncSetAttribute(attn_kernel, cudaFuncAttributeMaxDynamicSharedMemorySize, ATTN_SMEM);
    attn_kernel<<<dim3(S / 64, B * H), 256, ATTN_SMEM>>>(
        (const float*)p_qr, (const float*)p_kr, (const float*)p_vt,
        (const float*)p_qg, (float*)p_attn);

    // 4) output projection -> d_out
    sgemm_kernel<<<dim3(HID / 128, M / 128), 256>>>((const float*)p_attn, Wo, out, M, HID, H * D);
}

// round 14
// speedup vs baseline: 1.2051x; 1.2051x over previous
#include <cuda_runtime.h>
#include <cuda_bf16.h>
#include <math.h>
#include <cstdint>

// Problem constants
constexpr int B   = 2;
constexpr int S   = 2048;
constexpr int HID = 2048;
constexpr int H   = 16;
constexpr int KV  = 4;
constexpr int D   = 128;
constexpr int G   = H / KV;           // 4
constexpr float EPS = 1e-6f;
constexpr float SCALE = 0.08838834764831845f; // 128^-0.5

// ---------------- scratch (static device globals; no runtime alloc) -------
__device__ float g_qg  [(size_t)B * S * 2 * H * D];   // [B,S,4096] q||gate
__device__ float g_kbuf[(size_t)B * S * KV * D];      // [B,S,512]
__device__ float g_vbuf[(size_t)B * S * KV * D];      // [B,S,512]
__device__ float g_qr  [(size_t)B * H * S * D];       // [B,H,S,D]
__device__ float g_kr  [(size_t)B * KV * S * D];      // [B,KV,S,D]
__device__ float g_vt  [(size_t)B * KV * S * D];      // [B,KV,S,D]
__device__ float g_attn[(size_t)B * S * H * D];       // [B,S,H*D]

// bf16 split buffers (hi + lo)
__device__ __align__(16) __nv_bfloat16 g_hid_h[(size_t)B * S * HID];
__device__ __align__(16) __nv_bfloat16 g_hid_l[(size_t)B * S * HID];
__device__ __align__(16) __nv_bfloat16 g_Wq_h[(size_t)4096 * 2048];   // [N,K] transposed
__device__ __align__(16) __nv_bfloat16 g_Wq_l[(size_t)4096 * 2048];
__device__ __align__(16) __nv_bfloat16 g_Wk_h[(size_t)512 * 2048];
__device__ __align__(16) __nv_bfloat16 g_Wk_l[(size_t)512 * 2048];
__device__ __align__(16) __nv_bfloat16 g_Wv_h[(size_t)512 * 2048];
__device__ __align__(16) __nv_bfloat16 g_Wv_l[(size_t)512 * 2048];
__device__ __align__(16) __nv_bfloat16 g_Wo_h[(size_t)2048 * 2048];
__device__ __align__(16) __nv_bfloat16 g_Wo_l[(size_t)2048 * 2048];
__device__ __align__(16) __nv_bfloat16 g_at_h[(size_t)B * S * H * D];
__device__ __align__(16) __nv_bfloat16 g_at_l[(size_t)B * S * H * D];

// ================= helpers (baseline PTX only; NO sm_103a features) =======
__device__ __forceinline__ uint32_t smem_u32(const void* p) {
    uint32_t a;
    asm("{ .reg .u64 t; cvta.to.shared.u64 t, %1; cvt.u32.u64 %0, t; }" : "=r"(a) : "l"(p));
    return a;
}

__device__ __forceinline__ void ldsm_x4(uint32_t* r, uint32_t addr) {
    asm volatile("ldmatrix.sync.aligned.m8n8.x4.shared.b16 {%0,%1,%2,%3}, [%4];"
        : "=r"(r[0]), "=r"(r[1]), "=r"(r[2]), "=r"(r[3]) : "r"(addr));
}

__device__ __forceinline__ void mma16816(float* d, const uint32_t* a,
                                         uint32_t b0, uint32_t b1) {
    asm volatile(
        "mma.sync.aligned.m16n8k16.row.col.f32.bf16.bf16.f32 "
        "{%0,%1,%2,%3}, {%4,%5,%6,%7}, {%8,%9}, {%0,%1,%2,%3};"
        : "+f"(d[0]), "+f"(d[1]), "+f"(d[2]), "+f"(d[3])
        : "r"(a[0]), "r"(a[1]), "r"(a[2]), "r"(a[3]), "r"(b0), "r"(b1));
}

#define CP_ASYNC16(dst, src) \
    asm volatile("cp.async.cg.shared.global [%0], [%1], 16;" :: "r"(dst), "l"(src))
#define CP_COMMIT() asm volatile("cp.async.commit_group;" ::: "memory")

// ================= split / transpose-split conversions =====================
__global__ __launch_bounds__(256) void split_kernel(
    const float* __restrict__ x, __nv_bfloat16* __restrict__ hi,
    __nv_bfloat16* __restrict__ lo, int n4)
{
    int i = blockIdx.x * 256 + threadIdx.x;
    if (i >= n4) return;
    float4 v = ((const float4*)x)[i];
    __nv_bfloat16 h[4], l[4];
    float vv[4] = {v.x, v.y, v.z, v.w};
#pragma unroll
    for (int j = 0; j < 4; j++) {
        h[j] = __float2bfloat16_rn(vv[j]);
        l[j] = __float2bfloat16_rn(vv[j] - __bfloat162float(h[j]));
    }
    ((uint2*)hi)[i] = *(uint2*)h;
    ((uint2*)lo)[i] = *(uint2*)l;
}

// W[K,N] fp32 -> Thi/Tlo [N,K] bf16
__global__ __launch_bounds__(256) void tsplit_kernel(
    const float* __restrict__ W, __nv_bfloat16* __restrict__ Thi,
    __nv_bfloat16* __restrict__ Tlo, int K, int N)
{
    __shared__ float t[32][33];
    const int n0 = blockIdx.x * 32, k0 = blockIdx.y * 32;
    const int tx = threadIdx.x, ty = threadIdx.y;   // (32, 8)
#pragma unroll
    for (int i = 0; i < 32; i += 8)
        t[ty + i][tx] = W[(size_t)(k0 + ty + i) * N + n0 + tx];
    __syncthreads();
#pragma unroll
    for (int i = 0; i < 32; i += 8) {
        float v = t[tx][ty + i];
        __nv_bfloat16 h = __float2bfloat16_rn(v);
        __nv_bfloat16 l = __float2bfloat16_rn(v - __bfloat162float(h));
        size_t o = (size_t)(n0 + ty + i) * K + k0 + tx;
        Thi[o] = h;
        Tlo[o] = l;
    }
}

// ================= mma.sync split-bf16 GEMM (baseline PTX, HMMA path) ======
// C[M,N] = A[M,K] @ Bt[N,K]^T, fp32 accuracy via hi/lo split (3 passes).
// CTA 128x128, K-chunk 32 bf16, 8 warps (warp tile 64x32),
// cp.async double-buffered smem, ldmatrix + m16n8k16 bf16 MMA.
constexpr int ROWE = 40;                       // padded row, bf16 elements (80B: ldmatrix conflict-free)
constexpr int MATE = 128 * ROWE;               // one matrix tile, elements
constexpr int STGE = 4 * MATE;                 // stage = Ah,Al,Bh,Bl
constexpr int GEMM_SMEM = 2 * STGE * 2;        // bytes = 81920

__global__ __launch_bounds__(256, 1) void gemm_mma_kernel(
    const __nv_bfloat16* __restrict__ Ahi, const __nv_bfloat16* __restrict__ Alo,
    const __nv_bfloat16* __restrict__ Bhi, const __nv_bfloat16* __restrict__ Blo,
    float* __restrict__ C, int M, int N, int K)
{
    extern __shared__ __align__(16) __nv_bfloat16 sm[];
    const int tid = threadIdx.x;
    const int wid = tid >> 5, lane = tid & 31;
    const int m0 = blockIdx.y * 128, n0 = blockIdx.x * 128;
    const int wm = (wid >> 2) * 64;     // warp m-offset within tile (0/64)
    const int wn = (wid & 3) * 32;      // warp n-offset within tile (0/32/64/96)

    float acc[4][4][4];
#pragma unroll
    for (int a = 0; a < 4; a++)
#pragma unroll
        for (int b = 0; b < 4; b++)
#pragma unroll
            for (int c = 0; c < 4; c++) acc[a][b][c] = 0.f;

    const int nc = K >> 5;   // K/32 chunks

    // async load of one chunk into stage s: 4 mats x 128 rows x 4 x 16B
#define LOAD_CHUNK(cc, ss) do { \
        const int kc_ = (cc) << 5; \
        _Pragma("unroll") \
        for (int i_ = 0; i_ < 8; i_++) { \
            int u_ = tid + i_ * 256; \
            int mat_ = u_ >> 9, rem_ = u_ & 511, r_ = rem_ >> 2, seg_ = rem_ & 3; \
            const __nv_bfloat16* src_; int row_; \
            if (mat_ < 2) { src_ = (mat_ == 0 ? Ahi : Alo); row_ = m0 + r_; } \
            else          { src_ = (mat_ == 2 ? Bhi : Blo); row_ = n0 + r_; } \
            const __nv_bfloat16* g_ = src_ + (size_t)row_ * K + kc_ + seg_ * 8; \
            uint32_t d_ = smem_u32(sm + (ss) * STGE + mat_ * MATE + r_ * ROWE + seg_ * 8); \
            CP_ASYNC16(d_, g_); \
        } \
        CP_COMMIT(); \
    } while (0)

    LOAD_CHUNK(0, 0);

    for (int c = 0; c < nc; c++) {
        const int s = c & 1;
        if (c + 1 < nc) {
            LOAD_CHUNK(c + 1, s ^ 1);
            asm volatile("cp.async.wait_group 1;" ::: "memory");
        } else {
            asm volatile("cp.async.wait_group 0;" ::: "memory");
        }
        __syncthreads();

        const uint32_t stg = smem_u32(sm + s * STGE);
        const int lrow = lane & 15;
        const int lcol = (lane >> 4) * 8;

#pragma unroll
        for (int ks = 0; ks < 2; ks++) {
            const int coff = ks * 16 + lcol;
            uint32_t ah[4][4], al[4][4], bh[2][4], bl[2][4];
#pragma unroll
            for (int mf = 0; mf < 4; mf++) {
                uint32_t off = ((wm + mf * 16 + lrow) * ROWE + coff) * 2;
                ldsm_x4(ah[mf], stg + 0 * MATE * 2 + off);
                ldsm_x4(al[mf], stg + 1 * MATE * 2 + off);
            }
#pragma unroll
            for (int nb = 0; nb < 2; nb++) {
                uint32_t off = ((wn + nb * 16 + lrow) * ROWE + coff) * 2;
                ldsm_x4(bh[nb], stg + 2 * MATE * 2 + off);
                ldsm_x4(bl[nb], stg + 3 * MATE * 2 + off);
            }
#pragma unroll
            for (int mf = 0; mf < 4; mf++)
#pragma unroll
                for (int nf = 0; nf < 4; nf++) {
                    const int nb = nf >> 1, o = nf & 1;
                    uint32_t bh0 = bh[nb][o], bh1 = bh[nb][o + 2];
                    uint32_t bl0 = bl[nb][o], bl1 = bl[nb][o + 2];
                    mma16816(acc[mf][nf], ah[mf], bh0, bh1);
                    mma16816(acc[mf][nf], ah[mf], bl0, bl1);
                    mma16816(acc[mf][nf], al[mf], bh0, bh1);
                }
        }
        __syncthreads();
    }

    // epilogue: d-frag layout m16n8: d0,d1 -> row lane>>2, cols (lane&3)*2+{0,1}; d2,d3 -> row+8
#pragma unroll
    for (int mf = 0; mf < 4; mf++)
#pragma unroll
        for (int nf = 0; nf < 4; nf++) {
            int r0 = m0 + wm + mf * 16 + (lane >> 2);
            int c0 = n0 + wn + nf * 8 + (lane & 3) * 2;
            float2* p0 = (float2*)(C + (size_t)r0 * N + c0);
            float2* p1 = (float2*)(C + (size_t)(r0 + 8) * N + c0);
            *p0 = make_float2(acc[mf][nf][0], acc[mf][nf][1]);
            *p1 = make_float2(acc[mf][nf][2], acc[mf][nf][3]);
        }
#undef LOAD_CHUNK
}

// ---------------- RMSNorm + RoPE + transpose -------------------------------
__global__ __launch_bounds__(128) void normrope_kernel(
    const float* __restrict__ qg, const float* __restrict__ kbuf,
    const float* __restrict__ vbuf,
    const float* __restrict__ cosb, const float* __restrict__ sinb,
    const float* __restrict__ qw, const float* __restrict__ kw,
    float* __restrict__ q_out, float* __restrict__ k_out,
    float* __restrict__ v_out)
{
    const int unit = blockIdx.x;
    const int d = threadIdx.x;
    const int per_tok = H + 2 * KV;
    const int tok = unit / per_tok;
    const int sub = unit % per_tok;
    const int b = tok / S, s = tok % S;

    __shared__ float sh[D];
    __shared__ float red[4];

    if (sub >= H + KV) {
        int kv = sub - H - KV;
        v_out[(((size_t)(b * KV + kv)) * S + s) * D + d] =
            vbuf[(size_t)tok * (KV * D) + kv * D + d];
        return;
    }

    float x, w;
    size_t out_idx;
    if (sub < H) {
        int h = sub;
        x = qg[(size_t)tok * (2 * H * D) + h * D + d];
        w = qw[d];
        out_idx = (((size_t)(b * H + h)) * S + s) * D + d;
    } else {
        int kv = sub - H;
        x = kbuf[(size_t)tok * (KV * D) + kv * D + d];
        w = kw[d];
        out_idx = (((size_t)(b * KV + kv)) * S + s) * D + d;
    }

    float ss = x * x;
#pragma unroll
    for (int o = 16; o; o >>= 1) ss += __shfl_xor_sync(0xFFFFFFFFu, ss, o);
    if ((d & 31) == 0) red[d >> 5] = ss;
    __syncthreads();
    float tot = red[0] + red[1] + red[2] + red[3];
    float r = rsqrtf(tot * (1.f / D) + EPS);
    float xn = x * r * (1.f + w);

    sh[d] = xn;
    __syncthreads();
    float part = (d < 64) ? -sh[d + 64] : sh[d - 64];
    float c  = cosb[(size_t)tok * D + d];
    float sn = sinb[(size_t)tok * D + d];

    float* dst = (sub < H) ? q_out : k_out;
    dst[out_idx] = xn * c + part * sn;
}

// ---------------- Flash attention (fp32) + sigmoid gate epilogue ----------
constexpr int ATTN_SMEM = (3 * 64 * 132 + 64 * 68) * 4;

__global__ __launch_bounds__(256) void attn_kernel(
    const float* __restrict__ qr, const float* __restrict__ kr,
    const float* __restrict__ vr, const float* __restrict__ qg,
    float* __restrict__ attn_out)
{
    extern __shared__ float fsmem[];
    float* Qs = fsmem;
    float* Ks = Qs + 64 * 132;
    float* Vs = Ks + 64 * 132;
    float* Ss = Vs + 64 * 132;

    const int qb = blockIdx.x, bh = blockIdx.y;
    const int b = bh / H, h = bh % H;
    const int kvh = h / G;
    const int tid = threadIdx.x;
    const int q0 = qb * 64;

    const float* qbase = qr + (((size_t)(b * H + h)) * S + q0) * D;
    for (int i = tid; i < 2048; i += 256) {
        int row = i >> 5, c4 = (i & 31) * 4;
        *(float4*)&Qs[row * 132 + c4] = *(const float4*)(qbase + row * D + c4);
    }

    const int ty = tid >> 4, tx = tid & 15;
    const int qi4 = ty * 4, kj4 = tx * 4;
    const int qrow = tid >> 2, g = tid & 3;
    const int gq = q0 + qrow;

    float m = -1e30f, l = 0.f;
    float acc[32];
#pragma unroll
    for (int i = 0; i < 32; i++) acc[i] = 0.f;

    const float* kbase = kr + ((size_t)(b * KV + kvh)) * S * D;
    const float* vbase = vr + ((size_t)(b * KV + kvh)) * S * D;

    for (int kb = 0; kb <= qb; kb++) {
        const int k0 = kb * 64;
        __syncthreads();
        for (int i = tid; i < 2048; i += 256) {
            int row = i >> 5, c4 = (i & 31) * 4;
            *(float4*)&Ks[row * 132 + c4] = *(const float4*)(kbase + (size_t)(k0 + row) * D + c4);
            *(float4*)&Vs[row * 132 + c4] = *(const float4*)(vbase + (size_t)(k0 + row) * D + c4);
        }
        __syncthreads();

        float cacc[4][4];
#pragma unroll
        for (int i = 0; i < 4; i++)
#pragma unroll
            for (int j = 0; j < 4; j++) cacc[i][j] = 0.f;

#pragma unroll 8
        for (int dd = 0; dd < D; dd += 4) {
            float4 a[4], bb[4];
#pragma unroll
            for (int i = 0; i < 4; i++) a[i]  = *(const float4*)&Qs[(qi4 + i) * 132 + dd];
#pragma unroll
            for (int j = 0; j < 4; j++) bb[j] = *(const float4*)&Ks[(kj4 + j) * 132 + dd];
#pragma unroll
            for (int i = 0; i < 4; i++)
#pragma unroll
                for (int j = 0; j < 4; j++) {
                    cacc[i][j] += a[i].x * bb[j].x;
                    cacc[i][j] += a[i].y * bb[j].y;
                    cacc[i][j] += a[i].z * bb[j].z;
                    cacc[i][j] += a[i].w * bb[j].w;
                }
        }
#pragma unroll
        for (int i = 0; i < 4; i++)
#pragma unroll
            for (int j = 0; j < 4; j++)
                Ss[(qi4 + i) * 68 + kj4 + j] = cacc[i][j];
        __syncthreads();

        float pv[16];
        float mb = -1e30f;
#pragma unroll
        for (int jj = 0; jj < 16; jj++) {
            int j = g * 16 + jj;
            float sv = Ss[qrow * 68 + j] * SCALE + ((k0 + j) <= gq ? 0.f : -1e9f);
            pv[jj] = sv;
            mb = fmaxf(mb, sv);
        }
        mb = fmaxf(mb, __shfl_xor_sync(0xFFFFFFFFu, mb, 1));
        mb = fmaxf(mb, __shfl_xor_sync(0xFFFFFFFFu, mb, 2));
        float mnew = fmaxf(m, mb);
        float sum = 0.f;
#pragma unroll
        for (int jj = 0; jj < 16; jj++) {
            pv[jj] = __expf(pv[jj] - mnew);
            sum += pv[jj];
        }
        sum += __shfl_xor_sync(0xFFFFFFFFu, sum, 1);
        sum += __shfl_xor_sync(0xFFFFFFFFu, sum, 2);
        float alpha = __expf(m - mnew);
        l = l * alpha + sum;
        m = mnew;
#pragma unroll
        for (int jj = 0; jj < 16; jj++)
            Ss[qrow * 68 + g * 16 + jj] = pv[jj];
        __syncthreads();

#pragma unroll
        for (int i = 0; i < 32; i++) acc[i] *= alpha;
#pragma unroll 8
        for (int j = 0; j < 64; j++) {
            float pj = Ss[qrow * 68 + j];
            const float* vrow = &Vs[j * 132 + g * 32];
#pragma unroll
            for (int i = 0; i < 32; i++) acc[i] += pj * vrow[i];
        }
    }

    const int srow = q0 + qrow;
    const float inv = 1.f / l;
    const size_t gbase = ((size_t)(b * S + srow)) * (2 * H * D) + H * D + h * D + g * 32;
    const size_t obase = ((size_t)(b * S + srow)) * (H * D) + h * D + g * 32;
#pragma unroll
    for (int i = 0; i < 32; i++) {
        float gate = qg[gbase + i];
        float sg = 1.f / (1.f + __expf(-gate));
        attn_out[obase + i] = acc[i] * inv * sg;
    }
}

// ---------------- host launch ---------------------------------------------
extern "C" void kernel_launch(void* const* d_in, const int* in_sizes, int n_in,
                              void* d_out, int out_size)
{
    const float* hidden = (const float*)d_in[0];
    const float* cosb   = (const float*)d_in[1];
    const float* sinb   = (const float*)d_in[2];
    // d_in[3] attention_mask: analytically causal, unused
    const float* Wq = (const float*)d_in[4];
    const float* Wk = (const float*)d_in[5];
    const float* Wv = (const float*)d_in[6];
    const float* Wo = (const float*)d_in[7];
    const float* qw = (const float*)d_in[8];
    const float* kw = (const float*)d_in[9];
    float* out = (float*)d_out;

    void *p_qg, *p_kbuf, *p_vbuf, *p_qr, *p_kr, *p_vt, *p_attn;
    cudaGetSymbolAddress(&p_qg, g_qg);
    cudaGetSymbolAddress(&p_kbuf, g_kbuf);
    cudaGetSymbolAddress(&p_vbuf, g_vbuf);
    cudaGetSymbolAddress(&p_qr, g_qr);
    cudaGetSymbolAddress(&p_kr, g_kr);
    cudaGetSymbolAddress(&p_vt, g_vt);
    cudaGetSymbolAddress(&p_attn, g_attn);

    void *p_hh, *p_hl, *p_qh, *p_ql, *p_kh, *p_kl, *p_vh, *p_vl, *p_oh, *p_ol, *p_ah, *p_al;
    cudaGetSymbolAddress(&p_hh, g_hid_h); cudaGetSymbolAddress(&p_hl, g_hid_l);
    cudaGetSymbolAddress(&p_qh, g_Wq_h);  cudaGetSymbolAddress(&p_ql, g_Wq_l);
    cudaGetSymbolAddress(&p_kh, g_Wk_h);  cudaGetSymbolAddress(&p_kl, g_Wk_l);
    cudaGetSymbolAddress(&p_vh, g_Wv_h);  cudaGetSymbolAddress(&p_vl, g_Wv_l);
    cudaGetSymbolAddress(&p_oh, g_Wo_h);  cudaGetSymbolAddress(&p_ol, g_Wo_l);
    cudaGetSymbolAddress(&p_ah, g_at_h);  cudaGetSymbolAddress(&p_al, g_at_l);

    const int M = B * S;  // 4096

    cudaFuncSetAttribute(gemm_mma_kernel, cudaFuncAttributeMaxDynamicSharedMemorySize, GEMM_SMEM);
    cudaFuncSetAttribute(attn_kernel, cudaFuncAttributeMaxDynamicSharedMemorySize, ATTN_SMEM);

    // 0) conversions: hidden split; weights transpose+split
    {
        int n4 = (M * HID) / 4;
        split_kernel<<<(n4 + 255) / 256, 256>>>(hidden, (__nv_bfloat16*)p_hh, (__nv_bfloat16*)p_hl, n4);
    }
    tsplit_kernel<<<dim3(4096 / 32, 2048 / 32), dim3(32, 8)>>>(Wq, (__nv_bfloat16*)p_qh, (__nv_bfloat16*)p_ql, 2048, 4096);
    tsplit_kernel<<<dim3(512 / 32, 2048 / 32), dim3(32, 8)>>>(Wk, (__nv_bfloat16*)p_kh, (__nv_bfloat16*)p_kl, 2048, 512);
    tsplit_kernel<<<dim3(512 / 32, 2048 / 32), dim3(32, 8)>>>(Wv, (__nv_bfloat16*)p_vh, (__nv_bfloat16*)p_vl, 2048, 512);
    tsplit_kernel<<<dim3(2048 / 32, 2048 / 32), dim3(32, 8)>>>(Wo, (__nv_bfloat16*)p_oh, (__nv_bfloat16*)p_ol, 2048, 2048);

    // 1) projections (mma.sync split-bf16)
    gemm_mma_kernel<<<dim3(4096 / 128, M / 128), 256, GEMM_SMEM>>>(
        (const __nv_bfloat16*)p_hh, (const __nv_bfloat16*)p_hl,
        (const __nv_bfloat16*)p_qh, (const __nv_bfloat16*)p_ql,
        (float*)p_qg, M, 4096, 2048);
    gemm_mma_kernel<<<dim3(512 / 128, M / 128), 256, GEMM_SMEM>>>(
        (const __nv_bfloat16*)p_hh, (const __nv_bfloat16*)p_hl,
        (const __nv_bfloat16*)p_kh, (const __nv_bfloat16*)p_kl,
        (float*)p_kbuf, M, 512, 2048);
    gemm_mma_kernel<<<dim3(512 / 128, M / 128), 256, GEMM_SMEM>>>(
        (const __nv_bfloat16*)p_hh, (const __nv_bfloat16*)p_hl,
        (const __nv_bfloat16*)p_vh, (const __nv_bfloat16*)p_vl,
        (float*)p_vbuf, M, 512, 2048);

    // 2) rmsnorm + rope + transpose
    normrope_kernel<<<B * S * (H + 2 * KV), 128>>>(
        (const float*)p_qg, (const float*)p_kbuf, (const float*)p_vbuf,
        cosb, sinb, qw, kw,
        (float*)p_qr, (float*)p_kr, (float*)p_vt);

    // 3) flash attention + gate
    attn_kernel<<<dim3(S / 64, B * H), 256, ATTN_SMEM>>>(
        (const float*)p_qr, (const float*)p_kr, (const float*)p_vt,
        (const float*)p_qg, (float*)p_attn);

    // 4) split attn output, then Wo projection -> d_out
    {
        int n4 = (M * H * D) / 4;
        split_kernel<<<(n4 + 255) / 256, 256>>>((const float*)p_attn, (__nv_bfloat16*)p_ah, (__nv_bfloat16*)p_al, n4);
    }
    gemm_mma_kernel<<<dim3(2048 / 128, M / 128), 256, GEMM_SMEM>>>(
        (const __nv_bfloat16*)p_ah, (const __nv_bfloat16*)p_al,
        (const __nv_bfloat16*)p_oh, (const __nv_bfloat16*)p_ol,
        out, M, 2048, 2048);
}